// round 13
// baseline (speedup 1.0000x reference)
#include <cuda_runtime.h>
#include <math.h>

// Fixed problem shapes
#define TT 32      // T
#define NN 8       // neighbors
#define DD 64      // embedding dim
#define NRR 32     // num relations
#define TDOT_MAX 100352

// tdot[e] = dot(E[e], w3),  w3 = W @ a3
__device__ __align__(16) float g_tdot[TDOT_MAX];

// ---------------------------------------------------------------------------
// Kernel 1: g_tdot[e] = dot(E[e], w3). 1024 blocks x 256 threads.
// Each block folds w3 inline (64 threads, 16 KB W read — L2-hot, parallel),
// then each warp covers ~12 rows via a 2-way unrolled grid-stride loop
// (two independent load+reduce chains in flight). Pre-warms L2 with E.
// ---------------------------------------------------------------------------
__global__ __launch_bounds__(256) void ckgat_tdot(
    const float* __restrict__ E, const float* __restrict__ W,
    const float* __restrict__ aG, int NE)
{
    __shared__ float sw3[DD];
    const int tid  = threadIdx.x;
    const int lane = tid & 31;
    const int warp = tid >> 5;

    if (tid < DD) {
        float s = 0.f;
        #pragma unroll 8
        for (int j = 0; j < DD; j++) s += W[tid * DD + j] * aG[2 * DD + j];
        sw3[tid] = s;
    }
    __syncthreads();

    const float2 w = *(const float2*)&sw3[2 * lane];
    const int stride = gridDim.x * 8;              // warps in grid
    int r = blockIdx.x * 8 + warp;
    for (; r + stride < NE; r += 2 * stride) {
        // two independent rows in flight
        const float2 e0 = *(const float2*)&E[(long)r * DD + 2 * lane];
        const float2 e1 = *(const float2*)&E[(long)(r + stride) * DD + 2 * lane];
        float p0 = e0.x * w.x + e0.y * w.y;
        float p1 = e1.x * w.x + e1.y * w.y;
        #pragma unroll
        for (int off = 16; off; off >>= 1) {
            p0 += __shfl_xor_sync(0xffffffffu, p0, off);
            p1 += __shfl_xor_sync(0xffffffffu, p1, off);
        }
        if (lane == 0) {
            g_tdot[r] = p0;
            g_tdot[r + stride] = p1;
        }
    }
    if (r < NE) {
        const float2 e0 = *(const float2*)&E[(long)r * DD + 2 * lane];
        float p0 = e0.x * w.x + e0.y * w.y;
        #pragma unroll
        for (int off = 16; off; off >>= 1)
            p0 += __shfl_xor_sync(0xffffffffu, p0, off);
        if (lane == 0) g_tdot[r] = p0;
    }
}

// ---------------------------------------------------------------------------
// Kernel 2: main fused GAT. Block = b (512 blocks, 256 threads).
//   warps 0-3: user side (16 units/warp), warps 4-7: item side.
// Preamble: stage W -> sW; fold w1 = W@a1, w2 = W@a2 from sW;
//   rdot[r] = dot(R[r], w2).
// Phase A (half-warp split): lane = (half, q), q = lane&15, dims 4q..4q+3;
//   half 0 = neighbors 0-3, half 1 = neighbors 4-7.
//   logit = butterfly(dot64(eh, w1)) + rdot[r] + tdot[t_n]  (no et row loads)
// Phase B: batched matvec (8 units) vs sW, float4 x broadcasts, ELU, acc.
// ---------------------------------------------------------------------------
__global__ __launch_bounds__(256) void ckgat_fused(
    const int* __restrict__ items,
    const int* __restrict__ user_h,  const int* __restrict__ user_t,
    const int* __restrict__ user_nh, const int* __restrict__ user_nr, const int* __restrict__ user_nt,
    const int* __restrict__ item_h,  const int* __restrict__ item_t,
    const int* __restrict__ item_nh, const int* __restrict__ item_nr, const int* __restrict__ item_nt,
    const float* __restrict__ E,     // entity_emb [NE,64]
    const float* __restrict__ R,     // relation_emb [32,64]
    const float* __restrict__ W,     // W_GAT [64,64]
    const float* __restrict__ aG,    // a_GAT [3*64]
    float* __restrict__ out,
    int B, int L)
{
    __shared__ float  sW[DD * DD];       // 16 KB
    __shared__ float  sw1[DD];
    __shared__ float  sw2[DD];
    __shared__ float  srd[NRR];
    __shared__ float  sX[8][8][DD];      // warp, slot, dim: 16 KB
    __shared__ float2 sAcc[8][32];       // 2 KB

    const int tid  = threadIdx.x;
    const int lane = tid & 31;
    const int warp = tid >> 5;
    const int side = warp >> 2;          // 0 = user, 1 = item
    const int wu   = warp & 3;           // warp-in-side
    const int b    = blockIdx.x;
    const int half = lane >> 4;          // 0: neighbors 0-3, 1: neighbors 4-7
    const int q    = lane & 15;          // sublane: dims 4q..4q+3

    for (int i = tid; i < DD * DD; i += 256) sW[i] = W[i];
    __syncthreads();
    if (tid < DD) {
        float s0 = 0.f, s1 = 0.f;
        #pragma unroll 8
        for (int j = 0; j < DD; j++) {
            const float w = sW[tid * DD + j];
            s0 += w * aG[j];
            s1 += w * aG[DD + j];
        }
        sw1[tid] = s0;
        sw2[tid] = s1;
    }
    __syncthreads();
    if (tid < NRR) {
        float s = 0.f;
        #pragma unroll 8
        for (int d = 0; d < DD; d++) s += R[tid * DD + d] * sw2[d];
        srd[tid] = s;
    }
    __syncthreads();

    // Per-lane float4 slice of w1: dims 4q..4q+3
    const float4 w1q = *(const float4*)&sw1[4 * q];

    const int* nhp = side ? item_nh : user_nh;
    const int* nrp = side ? item_nr : user_nr;
    const int* ntp = side ? item_nt : user_nt;
    const int* tp  = side ? item_t  : user_t;

    float2 acc = make_float2(0.f, 0.f);

    const int nUnits  = L * TT;              // 64 for L=2
    const int perWarp = nUnits / 4;          // 16
    const int nBatch  = (perWarp + 7) / 8;   // 2

    for (int jb = 0; jb < nBatch; jb++) {
        const int nIn = (perWarp - jb * 8) < 8 ? (perWarp - jb * 8) : 8;

        // -------- Phase A: attention for nIn units; x -> sX --------
        for (int i = 0; i < nIn; i++) {
            const int u = wu + 4 * (jb * 8 + i);
            const int l = u >> 5;                  // layer (T=32)
            const int t = u & 31;
            const long b3 = ((long)l * B + b) * TT + t;
            const long b4 = b3 * NN;

            // This half's 4 neighbors
            const int4 nh4 = *(const int4*)&nhp[b4 + 4 * half];
            const int4 nt4 = *(const int4*)&ntp[b4 + 4 * half];
            const int4 nr4 = *(const int4*)&nrp[b4 + 4 * half];
            const int hj[4] = {nh4.x, nh4.y, nh4.z, nh4.w};
            const int tj[4] = {nt4.x, nt4.y, nt4.z, nt4.w};
            const int rj[4] = {nr4.x, nr4.y, nr4.z, nr4.w};

            float4 eh[4];
            float  pp[4];
            #pragma unroll
            for (int j = 0; j < 4; j++) {
                const float4 e = *(const float4*)&E[(long)hj[j] * DD + 4 * q];
                eh[j] = e;
                pp[j] = e.x * w1q.x + e.y * w1q.y + e.z * w1q.z + e.w * w1q.w;
            }
            // 4-stage butterfly within each 16-lane half
            #pragma unroll
            for (int j = 0; j < 4; j++) {
                #pragma unroll
                for (int off = 8; off; off >>= 1)
                    pp[j] += __shfl_xor_sync(0xffffffffu, pp[j], off);
            }
            // relation + tail-dot terms, leaky relu
            float m4 = -1e30f;
            #pragma unroll
            for (int j = 0; j < 4; j++) {
                float p = pp[j] + srd[rj[j]] + g_tdot[tj[j]];
                p = p > 0.f ? p : 0.2f * p;
                pp[j] = p;
                m4 = fmaxf(m4, p);
            }
            // softmax over all 8 neighbors (cross-half)
            const float m = fmaxf(m4, __shfl_xor_sync(0xffffffffu, m4, 16));
            float s4 = 0.f;
            #pragma unroll
            for (int j = 0; j < 4; j++) { pp[j] = __expf(pp[j] - m); s4 += pp[j]; }
            const float s = s4 + __shfl_xor_sync(0xffffffffu, s4, 16);
            const float inv = 1.f / s;

            // x partial = this half's weighted neighbors (+ target in half 0)
            float4 x = make_float4(0.f, 0.f, 0.f, 0.f);
            #pragma unroll
            for (int j = 0; j < 4; j++) {
                const float a_ = pp[j] * inv;
                x.x += a_ * eh[j].x;
                x.y += a_ * eh[j].y;
                x.z += a_ * eh[j].z;
                x.w += a_ * eh[j].w;
            }
            if (half == 0) {
                const int tix = tp[b3];
                const float4 tg = *(const float4*)&E[(long)tix * DD + 4 * q];
                x.x += tg.x; x.y += tg.y; x.z += tg.z; x.w += tg.w;
            }
            x.x += __shfl_xor_sync(0xffffffffu, x.x, 16);
            x.y += __shfl_xor_sync(0xffffffffu, x.y, 16);
            x.z += __shfl_xor_sync(0xffffffffu, x.z, 16);
            x.w += __shfl_xor_sync(0xffffffffu, x.w, 16);
            if (half == 0)
                *(float4*)&sX[warp][i][4 * q] = x;
        }
        __syncwarp();

        // -------- Phase B: batched matvec y_i = elu(x_i @ W) --------
        const float2* sW2v = (const float2*)sW;   // sW2v[d*32 + lane]
        float2 y[8];
        #pragma unroll
        for (int i = 0; i < 8; i++) y[i] = make_float2(0.f, 0.f);
        #pragma unroll 4
        for (int d4 = 0; d4 < DD / 4; d4++) {
            const float2 wr0 = sW2v[(d4 * 4 + 0) * 32 + lane];
            const float2 wr1 = sW2v[(d4 * 4 + 1) * 32 + lane];
            const float2 wr2 = sW2v[(d4 * 4 + 2) * 32 + lane];
            const float2 wr3 = sW2v[(d4 * 4 + 3) * 32 + lane];
            #pragma unroll
            for (int i = 0; i < 8; i++) {
                const float4 xv = *(const float4*)&sX[warp][i][d4 * 4];  // broadcast
                y[i].x += xv.x * wr0.x + xv.y * wr1.x + xv.z * wr2.x + xv.w * wr3.x;
                y[i].y += xv.x * wr0.y + xv.y * wr1.y + xv.z * wr2.y + xv.w * wr3.y;
            }
        }
        for (int i = 0; i < nIn; i++) {
            float y0 = y[i].x, y1 = y[i].y;
            y0 = y0 > 0.f ? y0 : (__expf(y0) - 1.f);
            y1 = y1 > 0.f ? y1 : (__expf(y1) - 1.f);
            acc.x += y0;
            acc.y += y1;
        }
        __syncwarp();
    }

    // Base term: mean over T of E[h0[b][t]]; dims {2*lane, 2*lane+1}
    {
        const int* hp = side ? item_h : user_h;
        const float sc = 1.f / (float)TT;
        for (int t = wu * 8; t < wu * 8 + 8; t++) {
            int hi = hp[(long)b * TT + t];
            float2 e = *(const float2*)&E[(long)hi * DD + 2 * lane];
            acc.x += e.x * sc;
            acc.y += e.y * sc;
        }
    }
    // Item-side extra: E[items[b]]
    if (side == 1 && wu == 0) {
        int ii = items[b];
        float2 e = *(const float2*)&E[(long)ii * DD + 2 * lane];
        acc.x += e.x;
        acc.y += e.y;
    }

    sAcc[warp][lane] = acc;
    __syncthreads();

    if (warp == 0) {
        float2 u = sAcc[0][lane];
        float2 v = sAcc[4][lane];
        #pragma unroll
        for (int w = 1; w < 4; w++) {
            u.x += sAcc[w][lane].x;     u.y += sAcc[w][lane].y;
            v.x += sAcc[4 + w][lane].x; v.y += sAcc[4 + w][lane].y;
        }
        float d = u.x * v.x + u.y * v.y;
        #pragma unroll
        for (int off = 16; off; off >>= 1)
            d += __shfl_xor_sync(0xffffffffu, d, off);
        if (lane == 0) out[b] = 1.f / (1.f + __expf(-d));
    }
}

// ---------------------------------------------------------------------------
// launch. Inputs (metadata order):
//  0 items, 1 user_h, 2 user_r, 3 user_t, 4 user_nh, 5 user_nr, 6 user_nt,
//  7 item_h, 8 item_r, 9 item_t, 10 item_nh, 11 item_nr, 12 item_nt,
//  13 entity_emb, 14 relation_emb, 15 W_GAT, 16 a_GAT
// ---------------------------------------------------------------------------
extern "C" void kernel_launch(void* const* d_in, const int* in_sizes, int n_in,
                              void* d_out, int out_size) {
    const int*   items   = (const int*)d_in[0];
    const int*   user_h  = (const int*)d_in[1];
    const int*   user_t  = (const int*)d_in[3];
    const int*   user_nh = (const int*)d_in[4];
    const int*   user_nr = (const int*)d_in[5];
    const int*   user_nt = (const int*)d_in[6];
    const int*   item_h  = (const int*)d_in[7];
    const int*   item_t  = (const int*)d_in[9];
    const int*   item_nh = (const int*)d_in[10];
    const int*   item_nr = (const int*)d_in[11];
    const int*   item_nt = (const int*)d_in[12];
    const float* E       = (const float*)d_in[13];
    const float* R       = (const float*)d_in[14];
    const float* W       = (const float*)d_in[15];
    const float* a       = (const float*)d_in[16];
    float* out = (float*)d_out;

    const int B = in_sizes[0];
    int L = in_sizes[1] / (B * TT);
    if (L < 1) L = 1;
    int NE = in_sizes[13] / DD;
    if (NE > TDOT_MAX) NE = TDOT_MAX;

    ckgat_tdot<<<1024, 256>>>(E, W, a, NE);
    ckgat_fused<<<B, 256>>>(items, user_h, user_t, user_nh, user_nr, user_nt,
                            item_h, item_t, item_nh, item_nr, item_nt,
                            E, R, W, a, out, B, L);
}

// round 14
// speedup vs baseline: 1.0464x; 1.0464x over previous
#include <cuda_runtime.h>
#include <math.h>

// Fixed problem shapes
#define TT 32      // T
#define NN 8       // neighbors
#define DD 64      // embedding dim
#define NRR 32     // num relations
#define TDOT_MAX 100352

// Per-entity logit tables: hdot[e]=dot(E[e],w1), tdot[e]=dot(E[e],w3)
__device__ __align__(16) float g_hdot[TDOT_MAX];
__device__ __align__(16) float g_tdot[TDOT_MAX];

// ---------------------------------------------------------------------------
// Kernel 1: build both tables in ONE sweep of E. 1024 blocks x 256 threads.
// Each block folds w1,w3 inline (64 threads, 16 KB W read, parallel), then
// warp-per-row with 2 rows in flight; per row: one float2 load feeds BOTH
// dots (4 interleaved butterfly chains across the 2 rows).
// ---------------------------------------------------------------------------
__global__ __launch_bounds__(256) void ckgat_tabs(
    const float* __restrict__ E, const float* __restrict__ W,
    const float* __restrict__ aG, int NE)
{
    __shared__ float sw1[DD];
    __shared__ float sw3[DD];
    const int tid  = threadIdx.x;
    const int lane = tid & 31;
    const int warp = tid >> 5;

    if (tid < DD) {
        float s1 = 0.f, s3 = 0.f;
        #pragma unroll 8
        for (int j = 0; j < DD; j++) {
            const float w = W[tid * DD + j];
            s1 += w * aG[j];
            s3 += w * aG[2 * DD + j];
        }
        sw1[tid] = s1;
        sw3[tid] = s3;
    }
    __syncthreads();

    const float2 w1 = *(const float2*)&sw1[2 * lane];
    const float2 w3 = *(const float2*)&sw3[2 * lane];
    const int stride = gridDim.x * 8;              // warps in grid
    int r = blockIdx.x * 8 + warp;
    for (; r + stride < NE; r += 2 * stride) {
        const float2 e0 = *(const float2*)&E[(long)r * DD + 2 * lane];
        const float2 e1 = *(const float2*)&E[(long)(r + stride) * DD + 2 * lane];
        float h0 = e0.x * w1.x + e0.y * w1.y;
        float t0 = e0.x * w3.x + e0.y * w3.y;
        float h1 = e1.x * w1.x + e1.y * w1.y;
        float t1 = e1.x * w3.x + e1.y * w3.y;
        #pragma unroll
        for (int off = 16; off; off >>= 1) {
            h0 += __shfl_xor_sync(0xffffffffu, h0, off);
            t0 += __shfl_xor_sync(0xffffffffu, t0, off);
            h1 += __shfl_xor_sync(0xffffffffu, h1, off);
            t1 += __shfl_xor_sync(0xffffffffu, t1, off);
        }
        if (lane == 0) {
            g_hdot[r] = h0;  g_tdot[r] = t0;
            g_hdot[r + stride] = h1;  g_tdot[r + stride] = t1;
        }
    }
    if (r < NE) {
        const float2 e0 = *(const float2*)&E[(long)r * DD + 2 * lane];
        float h0 = e0.x * w1.x + e0.y * w1.y;
        float t0 = e0.x * w3.x + e0.y * w3.y;
        #pragma unroll
        for (int off = 16; off; off >>= 1) {
            h0 += __shfl_xor_sync(0xffffffffu, h0, off);
            t0 += __shfl_xor_sync(0xffffffffu, t0, off);
        }
        if (lane == 0) { g_hdot[r] = h0;  g_tdot[r] = t0; }
    }
}

// ---------------------------------------------------------------------------
// Kernel 2: main fused GAT. Block = b (512 blocks, 256 threads).
//   warps 0-3: user side (16 units/warp), warps 4-7: item side.
// Preamble: stage W -> sW; fold w2 = W@a2; rdot[r] = dot(R[r], w2).
// Phase A per unit (full warp): logit = 3 table lookups (no dot, no long
//   butterfly); 8-lane softmax (6 shfl); x = E[t] + sum att_n * E[nh_n]
//   with eh row loads independent of the logit chain (overlap).
// Phase B: batched matvec (8 units) vs sW, float4 x broadcasts, ELU, acc.
// ---------------------------------------------------------------------------
__global__ __launch_bounds__(256) void ckgat_fused(
    const int* __restrict__ items,
    const int* __restrict__ user_h,  const int* __restrict__ user_t,
    const int* __restrict__ user_nh, const int* __restrict__ user_nr, const int* __restrict__ user_nt,
    const int* __restrict__ item_h,  const int* __restrict__ item_t,
    const int* __restrict__ item_nh, const int* __restrict__ item_nr, const int* __restrict__ item_nt,
    const float* __restrict__ E,     // entity_emb [NE,64]
    const float* __restrict__ R,     // relation_emb [32,64]
    const float* __restrict__ W,     // W_GAT [64,64]
    const float* __restrict__ aG,    // a_GAT [3*64]
    float* __restrict__ out,
    int B, int L)
{
    __shared__ float  sW[DD * DD];       // 16 KB
    __shared__ float  sw2[DD];
    __shared__ float  srd[NRR];
    __shared__ float  sX[8][8][DD];      // warp, slot, dim: 16 KB
    __shared__ float2 sAcc[8][32];       // 2 KB

    const int tid  = threadIdx.x;
    const int lane = tid & 31;
    const int warp = tid >> 5;
    const int side = warp >> 2;          // 0 = user, 1 = item
    const int wu   = warp & 3;           // warp-in-side
    const int b    = blockIdx.x;
    const int ln8  = lane & 7;           // neighbor owned by this lane (mod 8)

    for (int i = tid; i < DD * DD; i += 256) sW[i] = W[i];
    __syncthreads();
    if (tid < DD) {
        float s = 0.f;
        #pragma unroll 8
        for (int j = 0; j < DD; j++) s += sW[tid * DD + j] * aG[DD + j];
        sw2[tid] = s;
    }
    __syncthreads();
    if (tid < NRR) {
        float s = 0.f;
        #pragma unroll 8
        for (int d = 0; d < DD; d++) s += R[tid * DD + d] * sw2[d];
        srd[tid] = s;
    }
    __syncthreads();

    const int* nhp = side ? item_nh : user_nh;
    const int* nrp = side ? item_nr : user_nr;
    const int* ntp = side ? item_nt : user_nt;
    const int* tp  = side ? item_t  : user_t;

    float2 acc = make_float2(0.f, 0.f);

    const int nUnits  = L * TT;              // 64 for L=2
    const int perWarp = nUnits / 4;          // 16
    const int nBatch  = (perWarp + 7) / 8;   // 2

    for (int jb = 0; jb < nBatch; jb++) {
        const int nIn = (perWarp - jb * 8) < 8 ? (perWarp - jb * 8) : 8;

        // -------- Phase A: attention for nIn units; x -> sX --------
        for (int i = 0; i < nIn; i++) {
            const int u = wu + 4 * (jb * 8 + i);
            const int l = u >> 5;                  // layer (T=32)
            const int t = u & 31;
            const long b3 = ((long)l * B + b) * TT + t;
            const long b4 = b3 * NN;

            // Full neighbor id list (known immediately -> eh loads overlap logits)
            const int4 nA = *(const int4*)&nhp[b4];
            const int4 nB = *(const int4*)&nhp[b4 + 4];
            const int tix = tp[b3];

            // Per-lane logit for neighbor (lane&7): three table lookups
            const int hsel = nhp[b4 + ln8];
            const int rsel = nrp[b4 + ln8];
            const int tsel = ntp[b4 + ln8];
            float p = g_hdot[hsel] + srd[rsel] + g_tdot[tsel];
            p = p > 0.f ? p : 0.2f * p;

            // softmax over 8 neighbors (butterfly within 8-lane groups)
            float m = p;
            #pragma unroll
            for (int off = 4; off; off >>= 1)
                m = fmaxf(m, __shfl_xor_sync(0xffffffffu, m, off));
            const float ex = __expf(p - m);
            float s = ex;
            #pragma unroll
            for (int off = 4; off; off >>= 1)
                s += __shfl_xor_sync(0xffffffffu, s, off);
            const float att = ex / s;   // this lane's (lane&7) attention weight

            // x = E[t] + sum_n att_n * E[nh_n], dims {2*lane, 2*lane+1}
            float2 x = *(const float2*)&E[(long)tix * DD + 2 * lane];
            const int hj[NN] = {nA.x, nA.y, nA.z, nA.w, nB.x, nB.y, nB.z, nB.w};
            #pragma unroll
            for (int n = 0; n < NN; n++) {
                const float a_ = __shfl_sync(0xffffffffu, att, n);
                const float2 e = *(const float2*)&E[(long)hj[n] * DD + 2 * lane];
                x.x += a_ * e.x;
                x.y += a_ * e.y;
            }
            *(float2*)&sX[warp][i][2 * lane] = x;
        }
        __syncwarp();

        // -------- Phase B: batched matvec y_i = elu(x_i @ W) --------
        const float2* sW2v = (const float2*)sW;   // sW2v[d*32 + lane]
        float2 y[8];
        #pragma unroll
        for (int i = 0; i < 8; i++) y[i] = make_float2(0.f, 0.f);
        #pragma unroll 4
        for (int d4 = 0; d4 < DD / 4; d4++) {
            const float2 wr0 = sW2v[(d4 * 4 + 0) * 32 + lane];
            const float2 wr1 = sW2v[(d4 * 4 + 1) * 32 + lane];
            const float2 wr2 = sW2v[(d4 * 4 + 2) * 32 + lane];
            const float2 wr3 = sW2v[(d4 * 4 + 3) * 32 + lane];
            #pragma unroll
            for (int i = 0; i < 8; i++) {
                const float4 xv = *(const float4*)&sX[warp][i][d4 * 4];  // broadcast
                y[i].x += xv.x * wr0.x + xv.y * wr1.x + xv.z * wr2.x + xv.w * wr3.x;
                y[i].y += xv.x * wr0.y + xv.y * wr1.y + xv.z * wr2.y + xv.w * wr3.y;
            }
        }
        for (int i = 0; i < nIn; i++) {
            float y0 = y[i].x, y1 = y[i].y;
            y0 = y0 > 0.f ? y0 : (__expf(y0) - 1.f);
            y1 = y1 > 0.f ? y1 : (__expf(y1) - 1.f);
            acc.x += y0;
            acc.y += y1;
        }
        __syncwarp();
    }

    // Base term: mean over T of E[h0[b][t]]; dims {2*lane, 2*lane+1}
    {
        const int* hp = side ? item_h : user_h;
        const float sc = 1.f / (float)TT;
        for (int t = wu * 8; t < wu * 8 + 8; t++) {
            int hi = hp[(long)b * TT + t];
            float2 e = *(const float2*)&E[(long)hi * DD + 2 * lane];
            acc.x += e.x * sc;
            acc.y += e.y * sc;
        }
    }
    // Item-side extra: E[items[b]]
    if (side == 1 && wu == 0) {
        int ii = items[b];
        float2 e = *(const float2*)&E[(long)ii * DD + 2 * lane];
        acc.x += e.x;
        acc.y += e.y;
    }

    sAcc[warp][lane] = acc;
    __syncthreads();

    if (warp == 0) {
        float2 u = sAcc[0][lane];
        float2 v = sAcc[4][lane];
        #pragma unroll
        for (int w = 1; w < 4; w++) {
            u.x += sAcc[w][lane].x;     u.y += sAcc[w][lane].y;
            v.x += sAcc[4 + w][lane].x; v.y += sAcc[4 + w][lane].y;
        }
        float d = u.x * v.x + u.y * v.y;
        #pragma unroll
        for (int off = 16; off; off >>= 1)
            d += __shfl_xor_sync(0xffffffffu, d, off);
        if (lane == 0) out[b] = 1.f / (1.f + __expf(-d));
    }
}

// ---------------------------------------------------------------------------
// launch. Inputs (metadata order):
//  0 items, 1 user_h, 2 user_r, 3 user_t, 4 user_nh, 5 user_nr, 6 user_nt,
//  7 item_h, 8 item_r, 9 item_t, 10 item_nh, 11 item_nr, 12 item_nt,
//  13 entity_emb, 14 relation_emb, 15 W_GAT, 16 a_GAT
// ---------------------------------------------------------------------------
extern "C" void kernel_launch(void* const* d_in, const int* in_sizes, int n_in,
                              void* d_out, int out_size) {
    const int*   items   = (const int*)d_in[0];
    const int*   user_h  = (const int*)d_in[1];
    const int*   user_t  = (const int*)d_in[3];
    const int*   user_nh = (const int*)d_in[4];
    const int*   user_nr = (const int*)d_in[5];
    const int*   user_nt = (const int*)d_in[6];
    const int*   item_h  = (const int*)d_in[7];
    const int*   item_t  = (const int*)d_in[9];
    const int*   item_nh = (const int*)d_in[10];
    const int*   item_nr = (const int*)d_in[11];
    const int*   item_nt = (const int*)d_in[12];
    const float* E       = (const float*)d_in[13];
    const float* R       = (const float*)d_in[14];
    const float* W       = (const float*)d_in[15];
    const float* a       = (const float*)d_in[16];
    float* out = (float*)d_out;

    const int B = in_sizes[0];
    int L = in_sizes[1] / (B * TT);
    if (L < 1) L = 1;
    int NE = in_sizes[13] / DD;
    if (NE > TDOT_MAX) NE = TDOT_MAX;

    ckgat_tabs<<<1024, 256>>>(E, W, a, NE);
    ckgat_fused<<<B, 256>>>(items, user_h, user_t, user_nh, user_nr, user_nt,
                            item_h, item_t, item_nh, item_nr, item_nt,
                            E, R, W, a, out, B, L);
}

// round 15
// speedup vs baseline: 1.1817x; 1.1293x over previous
#include <cuda_runtime.h>
#include <math.h>

// Fixed problem shapes
#define TT 32      // T
#define NN 8       // neighbors
#define DD 64      // embedding dim
#define NRR 32     // num relations
#define TDOT_MAX 100352

// Per-entity logit tables: hdot[e]=dot(E[e],w1), tdot[e]=dot(E[e],w3)
__device__ __align__(16) float g_hdot[TDOT_MAX];
__device__ __align__(16) float g_tdot[TDOT_MAX];

// ---------------------------------------------------------------------------
// Kernel 1: build both tables in ONE sweep of E. 1024 blocks x 256 threads.
// W is staged into smem COALESCED first, then folded (the R14 version folded
// straight from global with a 32-lines-per-wavefront pattern — that was the
// 16 us; smem staging removes it). Then warp-per-row, 2 rows in flight.
// ---------------------------------------------------------------------------
__global__ __launch_bounds__(256) void ckgat_tabs(
    const float* __restrict__ E, const float* __restrict__ W,
    const float* __restrict__ aG, int NE)
{
    __shared__ float sW[DD * DD];   // 16 KB, staged coalesced
    __shared__ float sw1[DD];
    __shared__ float sw3[DD];
    const int tid  = threadIdx.x;
    const int lane = tid & 31;
    const int warp = tid >> 5;

    for (int i = tid; i < DD * DD; i += 256) sW[i] = W[i];
    __syncthreads();
    if (tid < DD) {
        float s1 = 0.f, s3 = 0.f;
        #pragma unroll 8
        for (int j = 0; j < DD; j++) {
            const float w = sW[tid * DD + j];
            s1 += w * aG[j];
            s3 += w * aG[2 * DD + j];
        }
        sw1[tid] = s1;
        sw3[tid] = s3;
    }
    __syncthreads();

    const float2 w1 = *(const float2*)&sw1[2 * lane];
    const float2 w3 = *(const float2*)&sw3[2 * lane];
    const int stride = gridDim.x * 8;              // warps in grid
    int r = blockIdx.x * 8 + warp;
    for (; r + stride < NE; r += 2 * stride) {
        const float2 e0 = *(const float2*)&E[(long)r * DD + 2 * lane];
        const float2 e1 = *(const float2*)&E[(long)(r + stride) * DD + 2 * lane];
        float h0 = e0.x * w1.x + e0.y * w1.y;
        float t0 = e0.x * w3.x + e0.y * w3.y;
        float h1 = e1.x * w1.x + e1.y * w1.y;
        float t1 = e1.x * w3.x + e1.y * w3.y;
        #pragma unroll
        for (int off = 16; off; off >>= 1) {
            h0 += __shfl_xor_sync(0xffffffffu, h0, off);
            t0 += __shfl_xor_sync(0xffffffffu, t0, off);
            h1 += __shfl_xor_sync(0xffffffffu, h1, off);
            t1 += __shfl_xor_sync(0xffffffffu, t1, off);
        }
        if (lane == 0) {
            g_hdot[r] = h0;  g_tdot[r] = t0;
            g_hdot[r + stride] = h1;  g_tdot[r + stride] = t1;
        }
    }
    if (r < NE) {
        const float2 e0 = *(const float2*)&E[(long)r * DD + 2 * lane];
        float h0 = e0.x * w1.x + e0.y * w1.y;
        float t0 = e0.x * w3.x + e0.y * w3.y;
        #pragma unroll
        for (int off = 16; off; off >>= 1) {
            h0 += __shfl_xor_sync(0xffffffffu, h0, off);
            t0 += __shfl_xor_sync(0xffffffffu, t0, off);
        }
        if (lane == 0) { g_hdot[r] = h0;  g_tdot[r] = t0; }
    }
}

// ---------------------------------------------------------------------------
// Kernel 2: main fused GAT. Block = b (512 blocks, 256 threads).
//   warps 0-3: user side (16 units/warp), warps 4-7: item side.
// Preamble: stage W -> sW; fold w2 = W@a2; rdot[r] = dot(R[r], w2).
// Phase A per unit (full warp): logit = 3 table lookups; 8-lane softmax;
//   x = E[t] + sum att_n * E[nh_n] (eh loads independent of logit chain).
// Phase B: batched matvec (8 units) vs sW, float4 x broadcasts, ELU, acc.
// ---------------------------------------------------------------------------
__global__ __launch_bounds__(256) void ckgat_fused(
    const int* __restrict__ items,
    const int* __restrict__ user_h,  const int* __restrict__ user_t,
    const int* __restrict__ user_nh, const int* __restrict__ user_nr, const int* __restrict__ user_nt,
    const int* __restrict__ item_h,  const int* __restrict__ item_t,
    const int* __restrict__ item_nh, const int* __restrict__ item_nr, const int* __restrict__ item_nt,
    const float* __restrict__ E,     // entity_emb [NE,64]
    const float* __restrict__ R,     // relation_emb [32,64]
    const float* __restrict__ W,     // W_GAT [64,64]
    const float* __restrict__ aG,    // a_GAT [3*64]
    float* __restrict__ out,
    int B, int L)
{
    __shared__ float  sW[DD * DD];       // 16 KB
    __shared__ float  sw2[DD];
    __shared__ float  srd[NRR];
    __shared__ float  sX[8][8][DD];      // warp, slot, dim: 16 KB
    __shared__ float2 sAcc[8][32];       // 2 KB

    const int tid  = threadIdx.x;
    const int lane = tid & 31;
    const int warp = tid >> 5;
    const int side = warp >> 2;          // 0 = user, 1 = item
    const int wu   = warp & 3;           // warp-in-side
    const int b    = blockIdx.x;
    const int ln8  = lane & 7;           // neighbor owned by this lane (mod 8)

    for (int i = tid; i < DD * DD; i += 256) sW[i] = W[i];
    __syncthreads();
    if (tid < DD) {
        float s = 0.f;
        #pragma unroll 8
        for (int j = 0; j < DD; j++) s += sW[tid * DD + j] * aG[DD + j];
        sw2[tid] = s;
    }
    __syncthreads();
    if (tid < NRR) {
        float s = 0.f;
        #pragma unroll 8
        for (int d = 0; d < DD; d++) s += R[tid * DD + d] * sw2[d];
        srd[tid] = s;
    }
    __syncthreads();

    const int* nhp = side ? item_nh : user_nh;
    const int* nrp = side ? item_nr : user_nr;
    const int* ntp = side ? item_nt : user_nt;
    const int* tp  = side ? item_t  : user_t;

    float2 acc = make_float2(0.f, 0.f);

    const int nUnits  = L * TT;              // 64 for L=2
    const int perWarp = nUnits / 4;          // 16
    const int nBatch  = (perWarp + 7) / 8;   // 2

    for (int jb = 0; jb < nBatch; jb++) {
        const int nIn = (perWarp - jb * 8) < 8 ? (perWarp - jb * 8) : 8;

        // -------- Phase A: attention for nIn units; x -> sX --------
        for (int i = 0; i < nIn; i++) {
            const int u = wu + 4 * (jb * 8 + i);
            const int l = u >> 5;                  // layer (T=32)
            const int t = u & 31;
            const long b3 = ((long)l * B + b) * TT + t;
            const long b4 = b3 * NN;

            // Full neighbor id list (known immediately -> eh loads overlap logits)
            const int4 nA = *(const int4*)&nhp[b4];
            const int4 nB = *(const int4*)&nhp[b4 + 4];
            const int tix = tp[b3];

            // Per-lane logit for neighbor (lane&7): three table lookups
            const int hsel = nhp[b4 + ln8];
            const int rsel = nrp[b4 + ln8];
            const int tsel = ntp[b4 + ln8];
            float p = g_hdot[hsel] + srd[rsel] + g_tdot[tsel];
            p = p > 0.f ? p : 0.2f * p;

            // softmax over 8 neighbors (butterfly within 8-lane groups)
            float m = p;
            #pragma unroll
            for (int off = 4; off; off >>= 1)
                m = fmaxf(m, __shfl_xor_sync(0xffffffffu, m, off));
            const float ex = __expf(p - m);
            float s = ex;
            #pragma unroll
            for (int off = 4; off; off >>= 1)
                s += __shfl_xor_sync(0xffffffffu, s, off);
            const float att = ex / s;   // this lane's (lane&7) attention weight

            // x = E[t] + sum_n att_n * E[nh_n], dims {2*lane, 2*lane+1}
            float2 x = *(const float2*)&E[(long)tix * DD + 2 * lane];
            const int hj[NN] = {nA.x, nA.y, nA.z, nA.w, nB.x, nB.y, nB.z, nB.w};
            #pragma unroll
            for (int n = 0; n < NN; n++) {
                const float a_ = __shfl_sync(0xffffffffu, att, n);
                const float2 e = *(const float2*)&E[(long)hj[n] * DD + 2 * lane];
                x.x += a_ * e.x;
                x.y += a_ * e.y;
            }
            *(float2*)&sX[warp][i][2 * lane] = x;
        }
        __syncwarp();

        // -------- Phase B: batched matvec y_i = elu(x_i @ W) --------
        const float2* sW2v = (const float2*)sW;   // sW2v[d*32 + lane]
        float2 y[8];
        #pragma unroll
        for (int i = 0; i < 8; i++) y[i] = make_float2(0.f, 0.f);
        #pragma unroll 4
        for (int d4 = 0; d4 < DD / 4; d4++) {
            const float2 wr0 = sW2v[(d4 * 4 + 0) * 32 + lane];
            const float2 wr1 = sW2v[(d4 * 4 + 1) * 32 + lane];
            const float2 wr2 = sW2v[(d4 * 4 + 2) * 32 + lane];
            const float2 wr3 = sW2v[(d4 * 4 + 3) * 32 + lane];
            #pragma unroll
            for (int i = 0; i < 8; i++) {
                const float4 xv = *(const float4*)&sX[warp][i][d4 * 4];  // broadcast
                y[i].x += xv.x * wr0.x + xv.y * wr1.x + xv.z * wr2.x + xv.w * wr3.x;
                y[i].y += xv.x * wr0.y + xv.y * wr1.y + xv.z * wr2.y + xv.w * wr3.y;
            }
        }
        for (int i = 0; i < nIn; i++) {
            float y0 = y[i].x, y1 = y[i].y;
            y0 = y0 > 0.f ? y0 : (__expf(y0) - 1.f);
            y1 = y1 > 0.f ? y1 : (__expf(y1) - 1.f);
            acc.x += y0;
            acc.y += y1;
        }
        __syncwarp();
    }

    // Base term: mean over T of E[h0[b][t]]; dims {2*lane, 2*lane+1}
    {
        const int* hp = side ? item_h : user_h;
        const float sc = 1.f / (float)TT;
        for (int t = wu * 8; t < wu * 8 + 8; t++) {
            int hi = hp[(long)b * TT + t];
            float2 e = *(const float2*)&E[(long)hi * DD + 2 * lane];
            acc.x += e.x * sc;
            acc.y += e.y * sc;
        }
    }
    // Item-side extra: E[items[b]]
    if (side == 1 && wu == 0) {
        int ii = items[b];
        float2 e = *(const float2*)&E[(long)ii * DD + 2 * lane];
        acc.x += e.x;
        acc.y += e.y;
    }

    sAcc[warp][lane] = acc;
    __syncthreads();

    if (warp == 0) {
        float2 u = sAcc[0][lane];
        float2 v = sAcc[4][lane];
        #pragma unroll
        for (int w = 1; w < 4; w++) {
            u.x += sAcc[w][lane].x;     u.y += sAcc[w][lane].y;
            v.x += sAcc[4 + w][lane].x; v.y += sAcc[4 + w][lane].y;
        }
        float d = u.x * v.x + u.y * v.y;
        #pragma unroll
        for (int off = 16; off; off >>= 1)
            d += __shfl_xor_sync(0xffffffffu, d, off);
        if (lane == 0) out[b] = 1.f / (1.f + __expf(-d));
    }
}

// ---------------------------------------------------------------------------
// launch. Inputs (metadata order):
//  0 items, 1 user_h, 2 user_r, 3 user_t, 4 user_nh, 5 user_nr, 6 user_nt,
//  7 item_h, 8 item_r, 9 item_t, 10 item_nh, 11 item_nr, 12 item_nt,
//  13 entity_emb, 14 relation_emb, 15 W_GAT, 16 a_GAT
// ---------------------------------------------------------------------------
extern "C" void kernel_launch(void* const* d_in, const int* in_sizes, int n_in,
                              void* d_out, int out_size) {
    const int*   items   = (const int*)d_in[0];
    const int*   user_h  = (const int*)d_in[1];
    const int*   user_t  = (const int*)d_in[3];
    const int*   user_nh = (const int*)d_in[4];
    const int*   user_nr = (const int*)d_in[5];
    const int*   user_nt = (const int*)d_in[6];
    const int*   item_h  = (const int*)d_in[7];
    const int*   item_t  = (const int*)d_in[9];
    const int*   item_nh = (const int*)d_in[10];
    const int*   item_nr = (const int*)d_in[11];
    const int*   item_nt = (const int*)d_in[12];
    const float* E       = (const float*)d_in[13];
    const float* R       = (const float*)d_in[14];
    const float* W       = (const float*)d_in[15];
    const float* a       = (const float*)d_in[16];
    float* out = (float*)d_out;

    const int B = in_sizes[0];
    int L = in_sizes[1] / (B * TT);
    if (L < 1) L = 1;
    int NE = in_sizes[13] / DD;
    if (NE > TDOT_MAX) NE = TDOT_MAX;

    ckgat_tabs<<<1024, 256>>>(E, W, a, NE);
    ckgat_fused<<<B, 256>>>(items, user_h, user_t, user_nh, user_nr, user_nt,
                            item_h, item_t, item_nh, item_nr, item_nt,
                            E, R, W, a, out, B, L);
}

// round 16
// speedup vs baseline: 1.1850x; 1.0028x over previous
#include <cuda_runtime.h>
#include <math.h>

// Fixed problem shapes
#define TT 32      // T
#define NN 8       // neighbors
#define DD 64      // embedding dim
#define NRR 32     // num relations
#define TDOT_MAX 100352

// Per-entity logit tables: hdot[e]=dot(E[e],w1), tdot[e]=dot(E[e],w3)
__device__ __align__(16) float g_hdot[TDOT_MAX];
__device__ __align__(16) float g_tdot[TDOT_MAX];

// ---------------------------------------------------------------------------
// Kernel 1: build both tables in ONE sweep of E. 1024 blocks x 256 threads.
// W is staged into smem COALESCED first, then folded (the R14 version folded
// straight from global with a 32-lines-per-wavefront pattern — that was the
// 16 us; smem staging removes it). Then warp-per-row, 2 rows in flight.
// ---------------------------------------------------------------------------
__global__ __launch_bounds__(256) void ckgat_tabs(
    const float* __restrict__ E, const float* __restrict__ W,
    const float* __restrict__ aG, int NE)
{
    __shared__ float sW[DD * DD];   // 16 KB, staged coalesced
    __shared__ float sw1[DD];
    __shared__ float sw3[DD];
    const int tid  = threadIdx.x;
    const int lane = tid & 31;
    const int warp = tid >> 5;

    for (int i = tid; i < DD * DD; i += 256) sW[i] = W[i];
    __syncthreads();
    if (tid < DD) {
        float s1 = 0.f, s3 = 0.f;
        #pragma unroll 8
        for (int j = 0; j < DD; j++) {
            const float w = sW[tid * DD + j];
            s1 += w * aG[j];
            s3 += w * aG[2 * DD + j];
        }
        sw1[tid] = s1;
        sw3[tid] = s3;
    }
    __syncthreads();

    const float2 w1 = *(const float2*)&sw1[2 * lane];
    const float2 w3 = *(const float2*)&sw3[2 * lane];
    const int stride = gridDim.x * 8;              // warps in grid
    int r = blockIdx.x * 8 + warp;
    for (; r + stride < NE; r += 2 * stride) {
        const float2 e0 = *(const float2*)&E[(long)r * DD + 2 * lane];
        const float2 e1 = *(const float2*)&E[(long)(r + stride) * DD + 2 * lane];
        float h0 = e0.x * w1.x + e0.y * w1.y;
        float t0 = e0.x * w3.x + e0.y * w3.y;
        float h1 = e1.x * w1.x + e1.y * w1.y;
        float t1 = e1.x * w3.x + e1.y * w3.y;
        #pragma unroll
        for (int off = 16; off; off >>= 1) {
            h0 += __shfl_xor_sync(0xffffffffu, h0, off);
            t0 += __shfl_xor_sync(0xffffffffu, t0, off);
            h1 += __shfl_xor_sync(0xffffffffu, h1, off);
            t1 += __shfl_xor_sync(0xffffffffu, t1, off);
        }
        if (lane == 0) {
            g_hdot[r] = h0;  g_tdot[r] = t0;
            g_hdot[r + stride] = h1;  g_tdot[r + stride] = t1;
        }
    }
    if (r < NE) {
        const float2 e0 = *(const float2*)&E[(long)r * DD + 2 * lane];
        float h0 = e0.x * w1.x + e0.y * w1.y;
        float t0 = e0.x * w3.x + e0.y * w3.y;
        #pragma unroll
        for (int off = 16; off; off >>= 1) {
            h0 += __shfl_xor_sync(0xffffffffu, h0, off);
            t0 += __shfl_xor_sync(0xffffffffu, t0, off);
        }
        if (lane == 0) { g_hdot[r] = h0;  g_tdot[r] = t0; }
    }
}

// ---------------------------------------------------------------------------
// Kernel 2: main fused GAT. Block = b (512 blocks, 256 threads).
//   warps 0-3: user side (16 units/warp), warps 4-7: item side.
// Preamble: stage W -> sW; fold w2 = W@a2; rdot[r] = dot(R[r], w2).
// Phase A per unit (full warp): logit = 3 table lookups; 8-lane softmax;
//   x = E[t] + sum att_n * E[nh_n] (eh loads independent of logit chain).
// Phase B: batched matvec (8 units) vs sW, float4 x broadcasts, ELU, acc.
// ---------------------------------------------------------------------------
__global__ __launch_bounds__(256) void ckgat_fused(
    const int* __restrict__ items,
    const int* __restrict__ user_h,  const int* __restrict__ user_t,
    const int* __restrict__ user_nh, const int* __restrict__ user_nr, const int* __restrict__ user_nt,
    const int* __restrict__ item_h,  const int* __restrict__ item_t,
    const int* __restrict__ item_nh, const int* __restrict__ item_nr, const int* __restrict__ item_nt,
    const float* __restrict__ E,     // entity_emb [NE,64]
    const float* __restrict__ R,     // relation_emb [32,64]
    const float* __restrict__ W,     // W_GAT [64,64]
    const float* __restrict__ aG,    // a_GAT [3*64]
    float* __restrict__ out,
    int B, int L)
{
    __shared__ float  sW[DD * DD];       // 16 KB
    __shared__ float  sw2[DD];
    __shared__ float  srd[NRR];
    __shared__ float  sX[8][8][DD];      // warp, slot, dim: 16 KB
    __shared__ float2 sAcc[8][32];       // 2 KB

    const int tid  = threadIdx.x;
    const int lane = tid & 31;
    const int warp = tid >> 5;
    const int side = warp >> 2;          // 0 = user, 1 = item
    const int wu   = warp & 3;           // warp-in-side
    const int b    = blockIdx.x;
    const int ln8  = lane & 7;           // neighbor owned by this lane (mod 8)

    for (int i = tid; i < DD * DD; i += 256) sW[i] = W[i];
    __syncthreads();
    if (tid < DD) {
        float s = 0.f;
        #pragma unroll 8
        for (int j = 0; j < DD; j++) s += sW[tid * DD + j] * aG[DD + j];
        sw2[tid] = s;
    }
    __syncthreads();
    if (tid < NRR) {
        float s = 0.f;
        #pragma unroll 8
        for (int d = 0; d < DD; d++) s += R[tid * DD + d] * sw2[d];
        srd[tid] = s;
    }
    __syncthreads();

    const int* nhp = side ? item_nh : user_nh;
    const int* nrp = side ? item_nr : user_nr;
    const int* ntp = side ? item_nt : user_nt;
    const int* tp  = side ? item_t  : user_t;

    float2 acc = make_float2(0.f, 0.f);

    const int nUnits  = L * TT;              // 64 for L=2
    const int perWarp = nUnits / 4;          // 16
    const int nBatch  = (perWarp + 7) / 8;   // 2

    for (int jb = 0; jb < nBatch; jb++) {
        const int nIn = (perWarp - jb * 8) < 8 ? (perWarp - jb * 8) : 8;

        // -------- Phase A: attention for nIn units; x -> sX --------
        for (int i = 0; i < nIn; i++) {
            const int u = wu + 4 * (jb * 8 + i);
            const int l = u >> 5;                  // layer (T=32)
            const int t = u & 31;
            const long b3 = ((long)l * B + b) * TT + t;
            const long b4 = b3 * NN;

            // Full neighbor id list (known immediately -> eh loads overlap logits)
            const int4 nA = *(const int4*)&nhp[b4];
            const int4 nB = *(const int4*)&nhp[b4 + 4];
            const int tix = tp[b3];

            // Per-lane logit for neighbor (lane&7): three table lookups
            const int hsel = nhp[b4 + ln8];
            const int rsel = nrp[b4 + ln8];
            const int tsel = ntp[b4 + ln8];
            float p = g_hdot[hsel] + srd[rsel] + g_tdot[tsel];
            p = p > 0.f ? p : 0.2f * p;

            // softmax over 8 neighbors (butterfly within 8-lane groups)
            float m = p;
            #pragma unroll
            for (int off = 4; off; off >>= 1)
                m = fmaxf(m, __shfl_xor_sync(0xffffffffu, m, off));
            const float ex = __expf(p - m);
            float s = ex;
            #pragma unroll
            for (int off = 4; off; off >>= 1)
                s += __shfl_xor_sync(0xffffffffu, s, off);
            const float att = ex / s;   // this lane's (lane&7) attention weight

            // x = E[t] + sum_n att_n * E[nh_n], dims {2*lane, 2*lane+1}
            float2 x = *(const float2*)&E[(long)tix * DD + 2 * lane];
            const int hj[NN] = {nA.x, nA.y, nA.z, nA.w, nB.x, nB.y, nB.z, nB.w};
            #pragma unroll
            for (int n = 0; n < NN; n++) {
                const float a_ = __shfl_sync(0xffffffffu, att, n);
                const float2 e = *(const float2*)&E[(long)hj[n] * DD + 2 * lane];
                x.x += a_ * e.x;
                x.y += a_ * e.y;
            }
            *(float2*)&sX[warp][i][2 * lane] = x;
        }
        __syncwarp();

        // -------- Phase B: batched matvec y_i = elu(x_i @ W) --------
        const float2* sW2v = (const float2*)sW;   // sW2v[d*32 + lane]
        float2 y[8];
        #pragma unroll
        for (int i = 0; i < 8; i++) y[i] = make_float2(0.f, 0.f);
        #pragma unroll 4
        for (int d4 = 0; d4 < DD / 4; d4++) {
            const float2 wr0 = sW2v[(d4 * 4 + 0) * 32 + lane];
            const float2 wr1 = sW2v[(d4 * 4 + 1) * 32 + lane];
            const float2 wr2 = sW2v[(d4 * 4 + 2) * 32 + lane];
            const float2 wr3 = sW2v[(d4 * 4 + 3) * 32 + lane];
            #pragma unroll
            for (int i = 0; i < 8; i++) {
                const float4 xv = *(const float4*)&sX[warp][i][d4 * 4];  // broadcast
                y[i].x += xv.x * wr0.x + xv.y * wr1.x + xv.z * wr2.x + xv.w * wr3.x;
                y[i].y += xv.x * wr0.y + xv.y * wr1.y + xv.z * wr2.y + xv.w * wr3.y;
            }
        }
        for (int i = 0; i < nIn; i++) {
            float y0 = y[i].x, y1 = y[i].y;
            y0 = y0 > 0.f ? y0 : (__expf(y0) - 1.f);
            y1 = y1 > 0.f ? y1 : (__expf(y1) - 1.f);
            acc.x += y0;
            acc.y += y1;
        }
        __syncwarp();
    }

    // Base term: mean over T of E[h0[b][t]]; dims {2*lane, 2*lane+1}
    {
        const int* hp = side ? item_h : user_h;
        const float sc = 1.f / (float)TT;
        for (int t = wu * 8; t < wu * 8 + 8; t++) {
            int hi = hp[(long)b * TT + t];
            float2 e = *(const float2*)&E[(long)hi * DD + 2 * lane];
            acc.x += e.x * sc;
            acc.y += e.y * sc;
        }
    }
    // Item-side extra: E[items[b]]
    if (side == 1 && wu == 0) {
        int ii = items[b];
        float2 e = *(const float2*)&E[(long)ii * DD + 2 * lane];
        acc.x += e.x;
        acc.y += e.y;
    }

    sAcc[warp][lane] = acc;
    __syncthreads();

    if (warp == 0) {
        float2 u = sAcc[0][lane];
        float2 v = sAcc[4][lane];
        #pragma unroll
        for (int w = 1; w < 4; w++) {
            u.x += sAcc[w][lane].x;     u.y += sAcc[w][lane].y;
            v.x += sAcc[4 + w][lane].x; v.y += sAcc[4 + w][lane].y;
        }
        float d = u.x * v.x + u.y * v.y;
        #pragma unroll
        for (int off = 16; off; off >>= 1)
            d += __shfl_xor_sync(0xffffffffu, d, off);
        if (lane == 0) out[b] = 1.f / (1.f + __expf(-d));
    }
}

// ---------------------------------------------------------------------------
// launch. Inputs (metadata order):
//  0 items, 1 user_h, 2 user_r, 3 user_t, 4 user_nh, 5 user_nr, 6 user_nt,
//  7 item_h, 8 item_r, 9 item_t, 10 item_nh, 11 item_nr, 12 item_nt,
//  13 entity_emb, 14 relation_emb, 15 W_GAT, 16 a_GAT
// ---------------------------------------------------------------------------
extern "C" void kernel_launch(void* const* d_in, const int* in_sizes, int n_in,
                              void* d_out, int out_size) {
    const int*   items   = (const int*)d_in[0];
    const int*   user_h  = (const int*)d_in[1];
    const int*   user_t  = (const int*)d_in[3];
    const int*   user_nh = (const int*)d_in[4];
    const int*   user_nr = (const int*)d_in[5];
    const int*   user_nt = (const int*)d_in[6];
    const int*   item_h  = (const int*)d_in[7];
    const int*   item_t  = (const int*)d_in[9];
    const int*   item_nh = (const int*)d_in[10];
    const int*   item_nr = (const int*)d_in[11];
    const int*   item_nt = (const int*)d_in[12];
    const float* E       = (const float*)d_in[13];
    const float* R       = (const float*)d_in[14];
    const float* W       = (const float*)d_in[15];
    const float* a       = (const float*)d_in[16];
    float* out = (float*)d_out;

    const int B = in_sizes[0];
    int L = in_sizes[1] / (B * TT);
    if (L < 1) L = 1;
    int NE = in_sizes[13] / DD;
    if (NE > TDOT_MAX) NE = TDOT_MAX;

    ckgat_tabs<<<1024, 256>>>(E, W, a, NE);
    ckgat_fused<<<B, 256>>>(items, user_h, user_t, user_nh, user_nr, user_nt,
                            item_h, item_t, item_nh, item_nr, item_nt,
                            E, R, W, a, out, B, L);
}